// round 14
// baseline (speedup 1.0000x reference)
#include <cuda_runtime.h>
#include <cuda_fp16.h>
#include <cstdint>

#define NB 4096
#define NT 200
#define ND 64
#define NH1 128
#define NH2 64
#define NTHREADS 416   // 13 warps: exactly one m16 tile per warp

// fp16 tiles, natural row pitch (128B/256B), per-row chunk-XOR swizzle:
// physical_16B_chunk = logical_chunk ^ (row & 7).
struct __align__(16) Smem {
    char Ahi[208 * 128];    // hist fp16 [208 rows][64]
    char B1hi[128 * 128];   // Weff^T fp16 [128 n][64 k]
    char B2hi[64 * 256];    // W2^T fp16 [64 n][128 k]
    float u[NH1];
    float b2s[NH2], w3s[NH2];
    float scores[208];
    float weights[NT];
    float partial[6][ND];
    float invsum;
};

__device__ __forceinline__ uint32_t smem_u32(const void* p) {
    uint32_t a;
    asm("{ .reg .u64 t; cvta.to.shared.u64 t, %1; cvt.u32.u64 %0, t; }" : "=r"(a) : "l"(p));
    return a;
}
__device__ __forceinline__ void ldsm4(uint32_t* r, uint32_t addr) {
    asm volatile("ldmatrix.sync.aligned.m8n8.x4.shared.b16 {%0,%1,%2,%3}, [%4];"
        : "=r"(r[0]), "=r"(r[1]), "=r"(r[2]), "=r"(r[3]) : "r"(addr));
}
__device__ __forceinline__ void mma16816(float* c, const uint32_t* a, const uint32_t* b) {
    asm volatile("mma.sync.aligned.m16n8k16.row.col.f32.f16.f16.f32 "
        "{%0,%1,%2,%3}, {%4,%5,%6,%7}, {%8,%9}, {%0,%1,%2,%3};"
        : "+f"(c[0]), "+f"(c[1]), "+f"(c[2]), "+f"(c[3])
        : "r"(a[0]), "r"(a[1]), "r"(a[2]), "r"(a[3]), "r"(b[0]), "r"(b[1]));
}
__device__ __forceinline__ uint32_t pack_h2(float x0, float x1) {
    __half2 h = __floats2half2_rn(x0, x1);
    return *reinterpret_cast<uint32_t*>(&h);
}

__global__ void __launch_bounds__(NTHREADS, 2)
attention_unit_kernel(const float* __restrict__ cand_g,
                      const float* __restrict__ hist_g,
                      const int*   __restrict__ mask_g,
                      const float* __restrict__ W1,
                      const float* __restrict__ b1,
                      const float* __restrict__ W2,
                      const float* __restrict__ b2,
                      const float* __restrict__ W3,
                      const float* __restrict__ b3,
                      float* __restrict__ out)
{
    extern __shared__ __align__(16) char smem_raw[];
    Smem& s = *reinterpret_cast<Smem*>(smem_raw);

    const int b    = blockIdx.x;
    const int tid  = threadIdx.x;
    const int warp = tid >> 5;
    const int lane = tid & 31;

    // =================== Phase 0: stage + convert ===================
    {
        const float4* hg = reinterpret_cast<const float4*>(hist_g + (size_t)b * NT * ND);
        for (int i = tid; i < NT * ND / 4; i += NTHREADS) {
            float4 v = hg[i];
            int t = i >> 4, q = i & 15;
            uint32_t off = (uint32_t)(t * 128 + (((q >> 1) ^ (t & 7)) << 4) + (q & 1) * 8);
            *reinterpret_cast<uint2*>(s.Ahi + off) =
                make_uint2(pack_h2(v.x, v.y), pack_h2(v.z, v.w));
        }
        if (tid < 128)   // zero pad rows 200..207
            reinterpret_cast<uint2*>(s.Ahi + 200 * 128)[tid] = make_uint2(0, 0);
    }
    // Weff^T[h][d] = W1[64+d][h] - W1[128+d][h] + c[d]*W1[192+d][h]
    for (int i = tid; i < NH1 * ND; i += NTHREADS) {
        int d = i >> 7, h = i & 127;
        float cd = __ldg(&cand_g[(size_t)b * ND + d]);
        float w = W1[(64 + d) * NH1 + h] - W1[(128 + d) * NH1 + h]
                + cd * W1[(192 + d) * NH1 + h];
        __half hw = __float2half_rn(w);
        uint32_t off = (uint32_t)(h * 128 + (((d >> 3) ^ (h & 7)) << 4) + (d & 7) * 2);
        *reinterpret_cast<uint16_t*>(s.B1hi + off) = *reinterpret_cast<uint16_t*>(&hw);
    }
    if (tid < NH1) {
        float acc = b1[tid];
        #pragma unroll 4
        for (int d = 0; d < ND; d++)
            acc += __ldg(&cand_g[(size_t)b * ND + d])
                 * (W1[d * NH1 + tid] + W1[(128 + d) * NH1 + tid]);
        s.u[tid] = acc;
    }
    for (int i = tid; i < NH1 * NH2; i += NTHREADS) {
        int k = i >> 6, j = i & 63;
        __half hw = __float2half_rn(W2[i]);
        uint32_t off = (uint32_t)(j * 256 + (((k >> 3) ^ (j & 7)) << 4) + (k & 7) * 2);
        *reinterpret_cast<uint16_t*>(s.B2hi + off) = *reinterpret_cast<uint16_t*>(&hw);
    }
    if (tid < NH2) { s.b2s[tid] = b2[tid]; s.w3s[tid] = W3[tid]; }
    __syncthreads();

    const uint32_t pAhi = smem_u32(s.Ahi);
    const uint32_t pB1h = smem_u32(s.B1hi);
    const uint32_t pB2h = smem_u32(s.B2hi);

    const int lrow = lane & 15, lkh = lane >> 4;
    const int bn   = ((lane >> 4) << 3) + (lane & 7);
    const int bk   = (lane >> 3) & 1;
    const float b3v = __ldg(&b3[0]);

    // ========== Fused per-warp pipeline: one m16 tile per warp ==========
    {
        const int mt   = warp;                  // 0..12, all warps
        const int arow = mt * 16 + lrow;

        uint32_t Ra[4][4];
        #pragma unroll
        for (int kk = 0; kk < 4; kk++)
            ldsm4(Ra[kk], pAhi + (uint32_t)(arow * 128 + (((kk * 2 + lkh) ^ (arow & 7)) << 4)));

        uint32_t Hfrag[8][4];                   // H m16 x k128 A-fragments

        // ---- GEMM1: four n-quarter passes (n=32 each) ----
        #pragma unroll
        for (int p4 = 0; p4 < 4; p4++) {
            float acc[4][4];
            #pragma unroll
            for (int j = 0; j < 4; j++)
                #pragma unroll
                for (int i = 0; i < 4; i++) acc[j][i] = 0.f;

            #pragma unroll
            for (int kk = 0; kk < 4; kk++) {
                #pragma unroll
                for (int q = 0; q < 2; q++) {
                    int brow = p4 * 32 + q * 16 + bn;
                    uint32_t boff = (uint32_t)(brow * 128 + (((kk * 2 + bk) ^ (brow & 7)) << 4));
                    uint32_t bh[4];
                    ldsm4(bh, pB1h + boff);
                    mma16816(acc[2 * q + 0], Ra[kk], &bh[0]);
                    mma16816(acc[2 * q + 1], Ra[kk], &bh[2]);
                }
            }
            #pragma unroll
            for (int j = 0; j < 4; j++) {
                int col = p4 * 32 + j * 8 + (lane & 3) * 2;
                float u0 = s.u[col], u1 = s.u[col + 1];
                float x0 = fmaxf(acc[j][0] + u0, 0.f);
                float x1 = fmaxf(acc[j][1] + u1, 0.f);
                float x2 = fmaxf(acc[j][2] + u0, 0.f);
                float x3 = fmaxf(acc[j][3] + u1, 0.f);
                int kb = p4 * 2 + (j >> 1), sub = (j & 1) * 2;
                Hfrag[kb][sub + 0] = pack_h2(x0, x1);
                Hfrag[kb][sub + 1] = pack_h2(x2, x3);
            }
        }

        // ---- GEMM2 (n=64, k=128) + GEMM3 ----
        float sc_lo = 0.f, sc_hi = 0.f;
        #pragma unroll
        for (int jp = 0; jp < 4; jp++) {
            float a2[2][4];
            #pragma unroll
            for (int g2 = 0; g2 < 2; g2++)
                #pragma unroll
                for (int i = 0; i < 4; i++) a2[g2][i] = 0.f;

            #pragma unroll
            for (int kk = 0; kk < 8; kk++) {
                int brow = jp * 16 + bn;
                uint32_t boff = (uint32_t)(brow * 256 + (((kk * 2 + bk) ^ (brow & 7)) << 4));
                uint32_t bh[4];
                ldsm4(bh, pB2h + boff);
                mma16816(a2[0], Hfrag[kk], &bh[0]);
                mma16816(a2[1], Hfrag[kk], &bh[2]);
            }
            #pragma unroll
            for (int g2 = 0; g2 < 2; g2++) {
                int col = jp * 16 + g2 * 8 + (lane & 3) * 2;
                float b20 = s.b2s[col], b21 = s.b2s[col + 1];
                float w30 = s.w3s[col], w31 = s.w3s[col + 1];
                sc_lo += fmaxf(a2[g2][0] + b20, 0.f) * w30 + fmaxf(a2[g2][1] + b21, 0.f) * w31;
                sc_hi += fmaxf(a2[g2][2] + b20, 0.f) * w30 + fmaxf(a2[g2][3] + b21, 0.f) * w31;
            }
        }
        sc_lo += __shfl_xor_sync(0xFFFFFFFFu, sc_lo, 1);
        sc_lo += __shfl_xor_sync(0xFFFFFFFFu, sc_lo, 2);
        sc_hi += __shfl_xor_sync(0xFFFFFFFFu, sc_hi, 1);
        sc_hi += __shfl_xor_sync(0xFFFFFFFFu, sc_hi, 2);
        if ((lane & 3) == 0) {
            int r = mt * 16 + (lane >> 2);
            s.scores[r] = sc_lo + b3v;
            int r2 = r + 8;
            if (r2 < NT) s.scores[r2] = sc_hi + b3v;
        }
    }
    __syncthreads();

    // ---- mask ----
    if (tid < NT) {
        float sc = s.scores[tid];
        if (mask_g[(size_t)b * NT + tid] == 0) sc = -1.0e9f;
        s.scores[tid] = sc;
    }
    __syncthreads();

    // ---- softmax (warp 0) ----
    if (tid < 32) {
        float m = -3.4e38f;
        for (int t = tid; t < NT; t += 32) m = fmaxf(m, s.scores[t]);
        #pragma unroll
        for (int o = 16; o; o >>= 1) m = fmaxf(m, __shfl_xor_sync(0xFFFFFFFFu, m, o));
        float sum = 0.f;
        for (int t = tid; t < NT; t += 32) {
            float e = __expf(s.scores[t] - m);
            s.weights[t] = e;
            sum += e;
        }
        #pragma unroll
        for (int o = 16; o; o >>= 1) sum += __shfl_xor_sync(0xFFFFFFFFu, sum, o);
        if (tid == 0) s.invsum = 1.0f / sum;
    }
    __syncthreads();

    // ---- out[b][d] = invsum * sum_t hist[t][d] * w[t] (hist reloaded, L2-hot) ----
    if (tid < 384) {
        int d = tid & (ND - 1);
        int g = tid >> 6;                  // 6 groups
        const float* hb = hist_g + (size_t)b * NT * ND;
        float acc = 0.f;
        for (int t = g; t < NT; t += 6) acc += hb[t * ND + d] * s.weights[t];
        s.partial[g][d] = acc;
    }
    __syncthreads();
    if (tid < ND) {
        float o = 0.f;
        #pragma unroll
        for (int g = 0; g < 6; g++) o += s.partial[g][tid];
        out[(size_t)b * ND + tid] = o * s.invsum;
    }
}

extern "C" void kernel_launch(void* const* d_in, const int* in_sizes, int n_in,
                              void* d_out, int out_size)
{
    const float* cand = (const float*)d_in[0];
    const float* hist = (const float*)d_in[1];
    const int*   mask = (const int*)  d_in[2];
    const float* W1   = (const float*)d_in[3];
    const float* b1   = (const float*)d_in[4];
    const float* W2   = (const float*)d_in[5];
    const float* b2   = (const float*)d_in[6];
    const float* W3   = (const float*)d_in[7];
    const float* b3   = (const float*)d_in[8];
    float* out        = (float*)d_out;

    const int smem = (int)sizeof(Smem);
    cudaFuncSetAttribute(attention_unit_kernel,
                         cudaFuncAttributeMaxDynamicSharedMemorySize, smem);

    attention_unit_kernel<<<NB, NTHREADS, smem>>>(cand, hist, mask, W1, b1, W2, b2, W3, b3, out);
}

// round 15
// speedup vs baseline: 1.4781x; 1.4781x over previous
#include <cuda_runtime.h>
#include <cuda_fp16.h>
#include <cstdint>

#define NB 4096
#define NT 200
#define ND 64
#define NH1 128
#define NH2 64
#define NTHREADS 256
#define NCTAS 444      // 3 CTAs/SM * 148 SMs, persistent

// fp16 tiles, natural row pitch (128B/256B), per-row chunk-XOR swizzle:
// physical_16B_chunk = logical_chunk ^ (row & 7).
struct __align__(16) Smem {
    char Ahi[208 * 128];    // hist fp16 [208 rows][64]
    char B1hi[128 * 128];   // Weff^T fp16 [128 n][64 k]   (per-batch)
    char B2hi[64 * 256];    // W2^T fp16 [64 n][128 k]     (batch-invariant, staged once)
    float u[NH1];
    float b2s[NH2], w3s[NH2];
    float scores[208];
    float weights[NT];
    float partial[4][ND];
    float invsum;
};

__device__ __forceinline__ uint32_t smem_u32(const void* p) {
    uint32_t a;
    asm("{ .reg .u64 t; cvta.to.shared.u64 t, %1; cvt.u32.u64 %0, t; }" : "=r"(a) : "l"(p));
    return a;
}
__device__ __forceinline__ void ldsm4(uint32_t* r, uint32_t addr) {
    asm volatile("ldmatrix.sync.aligned.m8n8.x4.shared.b16 {%0,%1,%2,%3}, [%4];"
        : "=r"(r[0]), "=r"(r[1]), "=r"(r[2]), "=r"(r[3]) : "r"(addr));
}
__device__ __forceinline__ void mma16816(float* c, const uint32_t* a, const uint32_t* b) {
    asm volatile("mma.sync.aligned.m16n8k16.row.col.f32.f16.f16.f32 "
        "{%0,%1,%2,%3}, {%4,%5,%6,%7}, {%8,%9}, {%0,%1,%2,%3};"
        : "+f"(c[0]), "+f"(c[1]), "+f"(c[2]), "+f"(c[3])
        : "r"(a[0]), "r"(a[1]), "r"(a[2]), "r"(a[3]), "r"(b[0]), "r"(b[1]));
}
__device__ __forceinline__ uint32_t pack_h2(float x0, float x1) {
    __half2 h = __floats2half2_rn(x0, x1);
    return *reinterpret_cast<uint32_t*>(&h);
}

__global__ void __launch_bounds__(NTHREADS, 3)
attention_unit_kernel(const float* __restrict__ cand_g,
                      const float* __restrict__ hist_g,
                      const int*   __restrict__ mask_g,
                      const float* __restrict__ W1,
                      const float* __restrict__ b1,
                      const float* __restrict__ W2,
                      const float* __restrict__ b2,
                      const float* __restrict__ W3,
                      const float* __restrict__ b3,
                      float* __restrict__ out)
{
    extern __shared__ __align__(16) char smem_raw[];
    Smem& s = *reinterpret_cast<Smem*>(smem_raw);

    const int tid  = threadIdx.x;
    const int warp = tid >> 5;
    const int lane = tid & 31;

    // ---- batch-invariant staging (once per CTA) ----
    for (int i = tid; i < NH1 * NH2; i += NTHREADS) {
        int k = i >> 6, j = i & 63;
        __half hw = __float2half_rn(W2[i]);
        uint32_t off = (uint32_t)(j * 256 + (((k >> 3) ^ (j & 7)) << 4) + (k & 7) * 2);
        *reinterpret_cast<uint16_t*>(s.B2hi + off) = *reinterpret_cast<uint16_t*>(&hw);
    }
    if (tid < NH2) { s.b2s[tid] = b2[tid]; s.w3s[tid] = W3[tid]; }
    if (tid < 128)   // zero pad Ahi rows 200..207 (stays zero across batches)
        reinterpret_cast<uint2*>(s.Ahi + 200 * 128)[tid] = make_uint2(0, 0);

    const uint32_t pAhi = smem_u32(s.Ahi);
    const uint32_t pB1h = smem_u32(s.B1hi);
    const uint32_t pB2h = smem_u32(s.B2hi);

    const int lrow = lane & 15, lkh = lane >> 4;
    const int bn   = ((lane >> 4) << 3) + (lane & 7);
    const int bk   = (lane >> 3) & 1;
    const float b3v = __ldg(&b3[0]);

    for (int b = blockIdx.x; b < NB; b += NCTAS) {
        __syncthreads();   // protect smem reuse across batch iterations

        // =================== Phase 0: stage + convert (per batch) ===================
        {
            const float4* hg = reinterpret_cast<const float4*>(hist_g + (size_t)b * NT * ND);
            for (int i = tid; i < NT * ND / 4; i += NTHREADS) {
                float4 v = hg[i];
                int t = i >> 4, q = i & 15;
                uint32_t off = (uint32_t)(t * 128 + (((q >> 1) ^ (t & 7)) << 4) + (q & 1) * 8);
                *reinterpret_cast<uint2*>(s.Ahi + off) =
                    make_uint2(pack_h2(v.x, v.y), pack_h2(v.z, v.w));
            }
        }
        // Weff^T[h][d] = W1[64+d][h] - W1[128+d][h] + c[d]*W1[192+d][h]
        {
            int h = tid & 127, half = tid >> 7;
            #pragma unroll 4
            for (int dd = 0; dd < 32; dd++) {
                int d = half * 32 + dd;
                float cd = __ldg(&cand_g[(size_t)b * ND + d]);
                float w = W1[(64 + d) * NH1 + h] - W1[(128 + d) * NH1 + h]
                        + cd * W1[(192 + d) * NH1 + h];
                __half hw = __float2half_rn(w);
                uint32_t off = (uint32_t)(h * 128 + (((d >> 3) ^ (h & 7)) << 4) + (d & 7) * 2);
                *reinterpret_cast<uint16_t*>(s.B1hi + off) = *reinterpret_cast<uint16_t*>(&hw);
            }
        }
        if (tid < NH1) {
            float acc = b1[tid];
            #pragma unroll 4
            for (int d = 0; d < ND; d++)
                acc += __ldg(&cand_g[(size_t)b * ND + d])
                     * (W1[d * NH1 + tid] + W1[(128 + d) * NH1 + tid]);
            s.u[tid] = acc;
        }
        __syncthreads();

        // ========== Fused per-warp pipeline: GEMM1 (quarter passes) -> H regs -> GEMM2 ==========
        #pragma unroll 1
        for (int task = 0; task < 2; task++) {
            int mt = warp + task * 8;
            if (mt > 12) break;
            const int arow = mt * 16 + lrow;

            uint32_t Ra[4][4];
            #pragma unroll
            for (int kk = 0; kk < 4; kk++)
                ldsm4(Ra[kk], pAhi + (uint32_t)(arow * 128 + (((kk * 2 + lkh) ^ (arow & 7)) << 4)));

            uint32_t Hfrag[8][4];

            #pragma unroll
            for (int p4 = 0; p4 < 4; p4++) {
                float acc[4][4];
                #pragma unroll
                for (int j = 0; j < 4; j++)
                    #pragma unroll
                    for (int i = 0; i < 4; i++) acc[j][i] = 0.f;

                #pragma unroll
                for (int kk = 0; kk < 4; kk++) {
                    #pragma unroll
                    for (int q = 0; q < 2; q++) {
                        int brow = p4 * 32 + q * 16 + bn;
                        uint32_t boff = (uint32_t)(brow * 128 + (((kk * 2 + bk) ^ (brow & 7)) << 4));
                        uint32_t bh[4];
                        ldsm4(bh, pB1h + boff);
                        mma16816(acc[2 * q + 0], Ra[kk], &bh[0]);
                        mma16816(acc[2 * q + 1], Ra[kk], &bh[2]);
                    }
                }
                #pragma unroll
                for (int j = 0; j < 4; j++) {
                    int col = p4 * 32 + j * 8 + (lane & 3) * 2;
                    float u0 = s.u[col], u1 = s.u[col + 1];
                    float x0 = fmaxf(acc[j][0] + u0, 0.f);
                    float x1 = fmaxf(acc[j][1] + u1, 0.f);
                    float x2 = fmaxf(acc[j][2] + u0, 0.f);
                    float x3 = fmaxf(acc[j][3] + u1, 0.f);
                    int kb = p4 * 2 + (j >> 1), sub = (j & 1) * 2;
                    Hfrag[kb][sub + 0] = pack_h2(x0, x1);
                    Hfrag[kb][sub + 1] = pack_h2(x2, x3);
                }
            }

            float sc_lo = 0.f, sc_hi = 0.f;
            #pragma unroll
            for (int jp = 0; jp < 4; jp++) {
                float a2[2][4];
                #pragma unroll
                for (int g2 = 0; g2 < 2; g2++)
                    #pragma unroll
                    for (int i = 0; i < 4; i++) a2[g2][i] = 0.f;

                #pragma unroll
                for (int kk = 0; kk < 8; kk++) {
                    int brow = jp * 16 + bn;
                    uint32_t boff = (uint32_t)(brow * 256 + (((kk * 2 + bk) ^ (brow & 7)) << 4));
                    uint32_t bh[4];
                    ldsm4(bh, pB2h + boff);
                    mma16816(a2[0], Hfrag[kk], &bh[0]);
                    mma16816(a2[1], Hfrag[kk], &bh[2]);
                }
                #pragma unroll
                for (int g2 = 0; g2 < 2; g2++) {
                    int col = jp * 16 + g2 * 8 + (lane & 3) * 2;
                    float b20 = s.b2s[col], b21 = s.b2s[col + 1];
                    float w30 = s.w3s[col], w31 = s.w3s[col + 1];
                    sc_lo += fmaxf(a2[g2][0] + b20, 0.f) * w30 + fmaxf(a2[g2][1] + b21, 0.f) * w31;
                    sc_hi += fmaxf(a2[g2][2] + b20, 0.f) * w30 + fmaxf(a2[g2][3] + b21, 0.f) * w31;
                }
            }
            sc_lo += __shfl_xor_sync(0xFFFFFFFFu, sc_lo, 1);
            sc_lo += __shfl_xor_sync(0xFFFFFFFFu, sc_lo, 2);
            sc_hi += __shfl_xor_sync(0xFFFFFFFFu, sc_hi, 1);
            sc_hi += __shfl_xor_sync(0xFFFFFFFFu, sc_hi, 2);
            if ((lane & 3) == 0) {
                int r = mt * 16 + (lane >> 2);
                s.scores[r] = sc_lo + b3v;
                int r2 = r + 8;
                if (r2 < NT) s.scores[r2] = sc_hi + b3v;
            }
        }
        __syncthreads();

        // ---- mask ----
        if (tid < NT) {
            float sc = s.scores[tid];
            if (mask_g[(size_t)b * NT + tid] == 0) sc = -1.0e9f;
            s.scores[tid] = sc;
        }
        __syncthreads();

        // ---- softmax (warp 0) ----
        if (tid < 32) {
            float m = -3.4e38f;
            for (int t = tid; t < NT; t += 32) m = fmaxf(m, s.scores[t]);
            #pragma unroll
            for (int o = 16; o; o >>= 1) m = fmaxf(m, __shfl_xor_sync(0xFFFFFFFFu, m, o));
            float sum = 0.f;
            for (int t = tid; t < NT; t += 32) {
                float e = __expf(s.scores[t] - m);
                s.weights[t] = e;
                sum += e;
            }
            #pragma unroll
            for (int o = 16; o; o >>= 1) sum += __shfl_xor_sync(0xFFFFFFFFu, sum, o);
            if (tid == 0) s.invsum = 1.0f / sum;
        }
        __syncthreads();

        // ---- out[b][d] = invsum * sum_t hist[t][d] * w[t] (hist reloaded, L2-hot) ----
        {
            int d = tid & (ND - 1);
            int g = tid >> 6;
            const float* hb = hist_g + (size_t)b * NT * ND;
            float acc = 0.f;
            for (int t = g; t < NT; t += 4) acc += hb[t * ND + d] * s.weights[t];
            s.partial[g][d] = acc;
        }
        __syncthreads();
        if (tid < ND) {
            float o = 0.f;
            #pragma unroll
            for (int g = 0; g < 4; g++) o += s.partial[g][tid];
            out[(size_t)b * ND + tid] = o * s.invsum;
        }
    }
}

extern "C" void kernel_launch(void* const* d_in, const int* in_sizes, int n_in,
                              void* d_out, int out_size)
{
    const float* cand = (const float*)d_in[0];
    const float* hist = (const float*)d_in[1];
    const int*   mask = (const int*)  d_in[2];
    const float* W1   = (const float*)d_in[3];
    const float* b1   = (const float*)d_in[4];
    const float* W2   = (const float*)d_in[5];
    const float* b2   = (const float*)d_in[6];
    const float* W3   = (const float*)d_in[7];
    const float* b3   = (const float*)d_in[8];
    float* out        = (float*)d_out;

    const int smem = (int)sizeof(Smem);
    cudaFuncSetAttribute(attention_unit_kernel,
                         cudaFuncAttributeMaxDynamicSharedMemorySize, smem);

    attention_unit_kernel<<<NCTAS, NTHREADS, smem>>>(cand, hist, mask, W1, b1, W2, b2, W3, b3, out);
}